// round 4
// baseline (speedup 1.0000x reference)
#include <cuda_runtime.h>
#include <cuda_fp16.h>
#include <cstdint>
#include <cstdio>

#define NN 100000
#define EE 1600000

// ---------------- device scratch (no allocations allowed) ----------------
__device__ float  g_B[4][16 * 18 * 64];          // prepacked weights, mma fragment layout, tf32
__device__ float  g_pre[(size_t)NN * 128];       // post-ELU h (fp32: feeds GEMM A)
__device__ __half g_hw[(size_t)NN * 128];        // h @ W (projected values, fp16)
__device__ float  g_ss[NN * 4];                  // s_src per head
__device__ float  g_sd[NN * 4];                  // s_dst per head
__device__ int    g_deg[NN];
__device__ int    g_rp[NN + 1];                  // CSR row_ptr (by edge_index[0])
__device__ int    g_wp[NN];
__device__ int    g_col[EE];                     // CSR col values
__device__ int    g_part[128];
__device__ int    g_poff[128];

// ---------------- helpers ----------------
__device__ __forceinline__ float eluf(float x) { return x > 0.f ? x : expm1f(x); }
__device__ __forceinline__ float lreluf(float x) { return fmaxf(x, 0.2f * x); }
__device__ __forceinline__ uint32_t to_tf32(float x) {
    uint32_t u; asm("cvt.rna.tf32.f32 %0, %1;" : "=r"(u) : "f"(x)); return u;
}
__device__ __forceinline__ void mma8(float* c, uint32_t a0, uint32_t a1, uint32_t a2,
                                     uint32_t a3, uint32_t b0, uint32_t b1) {
    asm("mma.sync.aligned.m16n8k8.row.col.f32.tf32.tf32.f32 "
        "{%0,%1,%2,%3}, {%4,%5,%6,%7}, {%8,%9}, {%0,%1,%2,%3};"
        : "+f"(c[0]), "+f"(c[1]), "+f"(c[2]), "+f"(c[3])
        : "r"(a0), "r"(a1), "r"(a2), "r"(a3), "r"(b0), "r"(b1));
}

// ---------------- weight prepack (fragment layout, tf32-rounded) ----------------
__global__ void pack_kernel(const float* __restrict__ Win,
                            const float* __restrict__ a_hid,
                            const float* __restrict__ W_hid,
                            const float* __restrict__ a_out,
                            const float* __restrict__ W_out) {
    int idx = blockIdx.x * blockDim.x + threadIdx.x;
    if (idx >= 4 * 16 * 18 * 64) return;
    int sel  = idx & 1;
    int lane = (idx >> 1) & 31;
    int tile = (idx >> 6) % 18;
    int step = (idx / (18 * 64)) % 16;
    int mat  = idx / (16 * 18 * 64);
    int k = step * 8 + (lane & 3) + sel * 4;
    int j = tile * 8 + (lane >> 2);
    float v = 0.f;
    if (mat == 0) {
        if (j < 128) v = Win[k * 128 + j];
    } else if (mat <= 2) {
        int l = mat - 1;
        if (j < 128) {
            int hd = j >> 5, jj = j & 31;
            v = W_hid[(((l * 4 + hd) * 128) + k) * 32 + jj];
        } else if (j < 132) {
            v = a_hid[((l * 4 + (j - 128)) * 2 + 0) * 128 + k];
        } else if (j < 136) {
            v = a_hid[((l * 4 + (j - 132)) * 2 + 1) * 128 + k];
        }
    } else {
        if (j < 64) v = W_out[k * 64 + j];
        else if (j == 64) v = a_out[k];
        else if (j == 68) v = a_out[128 + k];
    }
    g_B[mat][(step * 18 + tile) * 64 + lane * 2 + sel] = __uint_as_float(to_tf32(v));
}

// ---------------- CSR build ----------------
__global__ void zero_deg_kernel() {
    int i = blockIdx.x * blockDim.x + threadIdx.x;
    if (i < NN) g_deg[i] = 0;
}
__global__ void count_deg_kernel(const int* __restrict__ ei) {
    int e = blockIdx.x * blockDim.x + threadIdx.x;
    if (e < EE) atomicAdd(&g_deg[ei[e]], 1);
}
__global__ void scan_partial_kernel() {
    __shared__ int sm[1024];
    int i = blockIdx.x * 1024 + threadIdx.x;
    sm[threadIdx.x] = (i < NN) ? g_deg[i] : 0;
    __syncthreads();
    for (int o = 512; o > 0; o >>= 1) {
        if (threadIdx.x < o) sm[threadIdx.x] += sm[threadIdx.x + o];
        __syncthreads();
    }
    if (threadIdx.x == 0) g_part[blockIdx.x] = sm[0];
}
__global__ void scan_off_kernel() {
    __shared__ int sm[128];
    int t = threadIdx.x;
    const int nch = (NN + 1023) / 1024;
    int mine = (t < nch) ? g_part[t] : 0;
    sm[t] = mine;
    __syncthreads();
    for (int o = 1; o < 128; o <<= 1) {
        int v = (t >= o) ? sm[t - o] : 0;
        __syncthreads();
        sm[t] += v;
        __syncthreads();
    }
    g_poff[t] = sm[t] - mine;
    if (t == 0) g_rp[NN] = EE;
}
__global__ void scan_apply_kernel() {
    __shared__ int sm[1024];
    int t = threadIdx.x;
    int i = blockIdx.x * 1024 + t;
    int v = (i < NN) ? g_deg[i] : 0;
    sm[t] = v;
    __syncthreads();
    for (int o = 1; o < 1024; o <<= 1) {
        int u = (t >= o) ? sm[t - o] : 0;
        __syncthreads();
        sm[t] += u;
        __syncthreads();
    }
    if (i < NN) {
        int ex = sm[t] - v + g_poff[blockIdx.x];
        g_rp[i] = ex;
        g_wp[i] = ex;
    }
}
__global__ void fill_csr_kernel(const int* __restrict__ ei) {
    int e = blockIdx.x * blockDim.x + threadIdx.x;
    if (e < EE) {
        int r = ei[e];
        int p = atomicAdd(&g_wp[r], 1);
        g_col[p] = ei[EE + e];
    }
}

// ---------------- tf32 tensor-core GEMM ----------------
#define GEMM_SMEM_BYTES (16 * 18 * 64 * 4)

__global__ void __launch_bounds__(256, 2)
gemm_tc(const float* __restrict__ A, const float* __restrict__ Bf,
        float* __restrict__ Cf, __half* __restrict__ Ch,
        float* __restrict__ Ss, float* __restrict__ Sd,
        const float* __restrict__ bias, int M, int nhw, int elu_out, int write_s) {
    extern __shared__ float Bs[];
    const int tid = threadIdx.x;
    {
        const float4* src = (const float4*)Bf;
        float4* dst = (float4*)Bs;
        for (int i = tid; i < 16 * 18 * 16; i += 256) dst[i] = src[i];
    }
    __syncthreads();

    const int warp = tid >> 5, lane = tid & 31;
    const int g = lane >> 2, tg = lane & 3;
    const int r0 = blockIdx.x * 128 + warp * 16 + g;
    const int r1 = r0 + 8;
    const bool v0 = r0 < M, v1 = r1 < M;
    const float* A0 = A + (size_t)r0 * 128;
    const float* A1 = A + (size_t)r1 * 128;

    float acc[18][4];
#pragma unroll
    for (int t = 0; t < 18; t++)
#pragma unroll
        for (int c = 0; c < 4; c++) acc[t][c] = 0.f;

#pragma unroll 4
    for (int step = 0; step < 16; step++) {
        const int k = step * 8 + tg;
        uint32_t a0 = 0, a1 = 0, a2 = 0, a3 = 0;
        if (v0) { a0 = to_tf32(A0[k]); a2 = to_tf32(A0[k + 4]); }
        if (v1) { a1 = to_tf32(A1[k]); a3 = to_tf32(A1[k + 4]); }
        const float* bp = Bs + step * (18 * 64) + lane * 2;
#pragma unroll
        for (int t = 0; t < 18; t++) {
            float2 b = *(const float2*)(bp + t * 64);
            mma8(acc[t], a0, a1, a2, a3, __float_as_uint(b.x), __float_as_uint(b.y));
        }
    }

#pragma unroll
    for (int t = 0; t < 18; t++) {
        const int j = t * 8 + tg * 2;
        if (j < nhw) {
            float2 w0 = make_float2(acc[t][0], acc[t][1]);
            float2 w1 = make_float2(acc[t][2], acc[t][3]);
            if (bias) {
                float bx = bias[j], by = bias[j + 1];
                w0.x += bx; w0.y += by; w1.x += bx; w1.y += by;
            }
            if (elu_out) {
                w0.x = eluf(w0.x); w0.y = eluf(w0.y);
                w1.x = eluf(w1.x); w1.y = eluf(w1.y);
            }
            if (Cf) {
                if (v0) *(float2*)(Cf + (size_t)r0 * nhw + j) = w0;
                if (v1) *(float2*)(Cf + (size_t)r1 * nhw + j) = w1;
            } else {
                if (v0) *(__half2*)(Ch + (size_t)r0 * nhw + j) = __floats2half2_rn(w0.x, w0.y);
                if (v1) *(__half2*)(Ch + (size_t)r1 * nhw + j) = __floats2half2_rn(w1.x, w1.y);
            }
        } else if (write_s) {
            const int d = j - nhw;
            if (d < 4) {
                if (v0) { Ss[r0 * 4 + d] = acc[t][0]; Ss[r0 * 4 + d + 1] = acc[t][1]; }
                if (v1) { Ss[r1 * 4 + d] = acc[t][2]; Ss[r1 * 4 + d + 1] = acc[t][3]; }
            } else if (d < 8) {
                if (v0) { Sd[r0 * 4 + d - 4] = acc[t][0]; Sd[r0 * 4 + d - 3] = acc[t][1]; }
                if (v1) { Sd[r1 * 4 + d - 4] = acc[t][2]; Sd[r1 * 4 + d - 3] = acc[t][3]; }
            }
        }
    }
}

// ---------------- aggregation: warp per node, two-phase chunked ----------------
__global__ void __launch_bounds__(256)
agg_hidden_kernel(float* __restrict__ out) {
    __shared__ float4 s_w[8][32];
    __shared__ int    s_c[8][32];
    const int warp = threadIdx.x >> 5, lane = threadIdx.x & 31;
    const int node = blockIdx.x * 8 + warp;
    if (node >= NN) return;
    const int s = g_rp[node], e = g_rp[node + 1];
    float4* op = (float4*)(out + (size_t)node * 128);
    if (s == e) { op[lane] = make_float4(0.f, 0.f, 0.f, 0.f); return; }
    const float4 as = ((const float4*)g_ss)[node];
    const int head = lane >> 3;

    // ---- pass 1: per-head max (logits of first 32 edges kept in regs) ----
    float l0 = -1e30f, l1 = -1e30f, l2 = -1e30f, l3 = -1e30f;
    int c0 = 0;
    const int my0 = s + lane;
    if (my0 < e) {
        c0 = g_col[my0];
        float4 sd = ((const float4*)g_sd)[c0];
        l0 = lreluf(as.x + sd.x); l1 = lreluf(as.y + sd.y);
        l2 = lreluf(as.z + sd.z); l3 = lreluf(as.w + sd.w);
    }
    float m0 = l0, m1 = l1, m2 = l2, m3 = l3;
    for (int ei = s + 32 + lane; ei < e; ei += 32) {
        int c = g_col[ei];
        float4 sd = ((const float4*)g_sd)[c];
        m0 = fmaxf(m0, lreluf(as.x + sd.x));
        m1 = fmaxf(m1, lreluf(as.y + sd.y));
        m2 = fmaxf(m2, lreluf(as.z + sd.z));
        m3 = fmaxf(m3, lreluf(as.w + sd.w));
    }
#pragma unroll
    for (int o = 16; o > 0; o >>= 1) {
        m0 = fmaxf(m0, __shfl_xor_sync(~0u, m0, o));
        m1 = fmaxf(m1, __shfl_xor_sync(~0u, m1, o));
        m2 = fmaxf(m2, __shfl_xor_sync(~0u, m2, o));
        m3 = fmaxf(m3, __shfl_xor_sync(~0u, m3, o));
    }

    // ---- pass 2: chunked weight + feature accumulation (fp16 hw) ----
    float4 acc = make_float4(0.f, 0.f, 0.f, 0.f);
    float sw0 = 0.f, sw1 = 0.f, sw2 = 0.f, sw3 = 0.f;
    for (int cs = s; cs < e; cs += 32) {
        const int my = cs + lane;
        float w0 = 0.f, w1 = 0.f, w2 = 0.f, w3 = 0.f;
        int c = 0;
        if (my < e) {
            if (cs == s) {
                c = c0;
                w0 = __expf(l0 - m0); w1 = __expf(l1 - m1);
                w2 = __expf(l2 - m2); w3 = __expf(l3 - m3);
            } else {
                c = g_col[my];
                float4 sd = ((const float4*)g_sd)[c];
                w0 = __expf(lreluf(as.x + sd.x) - m0);
                w1 = __expf(lreluf(as.y + sd.y) - m1);
                w2 = __expf(lreluf(as.z + sd.z) - m2);
                w3 = __expf(lreluf(as.w + sd.w) - m3);
            }
            sw0 += w0; sw1 += w1; sw2 += w2; sw3 += w3;
        }
        s_w[warp][lane] = make_float4(w0, w1, w2, w3);
        s_c[warp][lane] = c;
        __syncwarp();
        const int n = min(32, e - cs);
#pragma unroll 4
        for (int j = 0; j < n; j++) {
            const int cc = s_c[warp][j];
            const float w = ((const float*)&s_w[warp][j])[head];
            const uint2 raw = *(const uint2*)(g_hw + (size_t)cc * 128 + lane * 4);
            const float2 f0 = __half22float2(*(const __half2*)&raw.x);
            const float2 f1 = __half22float2(*(const __half2*)&raw.y);
            acc.x += w * f0.x; acc.y += w * f0.y;
            acc.z += w * f1.x; acc.w += w * f1.y;
        }
        __syncwarp();
    }
#pragma unroll
    for (int o = 16; o > 0; o >>= 1) {
        sw0 += __shfl_xor_sync(~0u, sw0, o);
        sw1 += __shfl_xor_sync(~0u, sw1, o);
        sw2 += __shfl_xor_sync(~0u, sw2, o);
        sw3 += __shfl_xor_sync(~0u, sw3, o);
    }
    const float swh = (head == 0) ? sw0 : (head == 1) ? sw1 : (head == 2) ? sw2 : sw3;
    const float inv = __fdividef(1.f, swh);
    op[lane] = make_float4(eluf(acc.x * inv), eluf(acc.y * inv),
                           eluf(acc.z * inv), eluf(acc.w * inv));
}

// final: 1 head, 64 dims; lane owns dims 2l..2l+1.
__global__ void __launch_bounds__(256)
agg_final_kernel(float* __restrict__ out) {
    __shared__ float s_w[8][32];
    __shared__ int   s_c[8][32];
    const int warp = threadIdx.x >> 5, lane = threadIdx.x & 31;
    const int node = blockIdx.x * 8 + warp;
    if (node >= NN) return;
    const int s = g_rp[node], e = g_rp[node + 1];
    float2* op = (float2*)(out + (size_t)node * 64);
    if (s == e) { op[lane] = make_float2(0.f, 0.f); return; }
    const float as = g_ss[node * 4];

    float l0 = -1e30f;
    int c0 = 0;
    const int my0 = s + lane;
    if (my0 < e) { c0 = g_col[my0]; l0 = lreluf(as + g_sd[c0 * 4]); }
    float mm = l0;
    for (int ei = s + 32 + lane; ei < e; ei += 32)
        mm = fmaxf(mm, lreluf(as + g_sd[g_col[ei] * 4]));
#pragma unroll
    for (int o = 16; o > 0; o >>= 1) mm = fmaxf(mm, __shfl_xor_sync(~0u, mm, o));

    float2 acc = make_float2(0.f, 0.f);
    float sw = 0.f;
    for (int cs = s; cs < e; cs += 32) {
        const int my = cs + lane;
        float w = 0.f;
        int c = 0;
        if (my < e) {
            if (cs == s) { c = c0; w = __expf(l0 - mm); }
            else { c = g_col[my]; w = __expf(lreluf(as + g_sd[c * 4]) - mm); }
            sw += w;
        }
        s_w[warp][lane] = w;
        s_c[warp][lane] = c;
        __syncwarp();
        const int n = min(32, e - cs);
#pragma unroll 4
        for (int j = 0; j < n; j++) {
            const int cc = s_c[warp][j];
            const float w2 = s_w[warp][j];
            const float2 f = __half22float2(*(const __half2*)(g_hw + (size_t)cc * 64 + lane * 2));
            acc.x += w2 * f.x; acc.y += w2 * f.y;
        }
        __syncwarp();
    }
#pragma unroll
    for (int o = 16; o > 0; o >>= 1) sw += __shfl_xor_sync(~0u, sw, o);
    const float inv = __fdividef(1.f, sw);
    op[lane] = make_float2(acc.x * inv, acc.y * inv);
}

// ---------------- launch ----------------
extern "C" void kernel_launch(void* const* d_in, const int* in_sizes, int n_in,
                              void* d_out, int out_size) {
    const float* x     = (const float*)d_in[0];
    const int*   ei    = (const int*)d_in[1];
    const float* Win   = (const float*)d_in[2];
    const float* b_in  = (const float*)d_in[3];
    const float* a_hid = (const float*)d_in[4];
    const float* W_hid = (const float*)d_in[5];
    const float* a_out = (const float*)d_in[6];
    const float* W_out = (const float*)d_in[7];
    float* out = (float*)d_out;
    (void)in_sizes; (void)n_in; (void)out_size;

    cudaFuncSetAttribute(gemm_tc, cudaFuncAttributeMaxDynamicSharedMemorySize,
                         GEMM_SMEM_BYTES);

    float *pre, *ss, *sd, *bbase;
    __half* hw;
    cudaGetSymbolAddress((void**)&pre, g_pre);
    cudaGetSymbolAddress((void**)&hw, g_hw);
    cudaGetSymbolAddress((void**)&ss, g_ss);
    cudaGetSymbolAddress((void**)&sd, g_sd);
    cudaGetSymbolAddress((void**)&bbase, g_B);
    float* B0 = bbase;
    float* B1 = bbase + 16 * 18 * 64;
    float* B2 = bbase + 2 * 16 * 18 * 64;
    float* B3 = bbase + 3 * 16 * 18 * 64;

    pack_kernel<<<(4 * 16 * 18 * 64 + 255) / 256, 256>>>(Win, a_hid, W_hid, a_out, W_out);
    zero_deg_kernel<<<(NN + 255) / 256, 256>>>();
    count_deg_kernel<<<(EE + 255) / 256, 256>>>(ei);
    scan_partial_kernel<<<(NN + 1023) / 1024, 1024>>>();
    scan_off_kernel<<<1, 128>>>();
    scan_apply_kernel<<<(NN + 1023) / 1024, 1024>>>();
    fill_csr_kernel<<<(EE + 255) / 256, 256>>>(ei);

    const int gx = (NN + 127) / 128;
    const int ga = (NN + 7) / 8;

    gemm_tc<<<gx, 256, GEMM_SMEM_BYTES>>>(x, B0, pre, nullptr, nullptr, nullptr, b_in, NN, 128, 1, 0);
    gemm_tc<<<gx, 256, GEMM_SMEM_BYTES>>>(pre, B1, nullptr, hw, ss, sd, nullptr, NN, 128, 0, 1);
    agg_hidden_kernel<<<ga, 256>>>(pre);
    gemm_tc<<<gx, 256, GEMM_SMEM_BYTES>>>(pre, B2, nullptr, hw, ss, sd, nullptr, NN, 128, 0, 1);
    agg_hidden_kernel<<<ga, 256>>>(pre);
    gemm_tc<<<gx, 256, GEMM_SMEM_BYTES>>>(pre, B3, nullptr, hw, ss, sd, nullptr, NN, 64, 0, 1);
    agg_final_kernel<<<ga, 256>>>(out);
}

// round 5
// speedup vs baseline: 1.2281x; 1.2281x over previous
#include <cuda_runtime.h>
#include <cuda_fp16.h>
#include <cstdint>
#include <cstdio>

#define NN 100000
#define EE 1600000

// ---------------- device scratch (no allocations allowed) ----------------
__device__ uint32_t g_B[4][8 * 18 * 64];         // prepacked weights, f16 mma fragment layout
__device__ __half   g_pre[(size_t)NN * 128];     // post-ELU h (fp16: feeds GEMM A)
__device__ float    g_hw[(size_t)NN * 128];      // h @ W (projected values, fp32)
__device__ float    g_ss[NN * 4];                // s_src per head
__device__ float    g_sd[NN * 4];                // s_dst per head
__device__ int      g_deg[NN];
__device__ int      g_rp[NN + 1];                // CSR row_ptr (by edge_index[0])
__device__ int      g_wp[NN];
__device__ int      g_col[EE];                   // CSR col values
__device__ int      g_part[128];
__device__ int      g_poff[128];

// ---------------- helpers ----------------
__device__ __forceinline__ float eluf(float x) { return x > 0.f ? x : expm1f(x); }
__device__ __forceinline__ float lreluf(float x) { return fmaxf(x, 0.2f * x); }
__device__ __forceinline__ void mma16(float* c, uint32_t a0, uint32_t a1, uint32_t a2,
                                      uint32_t a3, uint32_t b0, uint32_t b1) {
    asm("mma.sync.aligned.m16n8k16.row.col.f32.f16.f16.f32 "
        "{%0,%1,%2,%3}, {%4,%5,%6,%7}, {%8,%9}, {%0,%1,%2,%3};"
        : "+f"(c[0]), "+f"(c[1]), "+f"(c[2]), "+f"(c[3])
        : "r"(a0), "r"(a1), "r"(a2), "r"(a3), "r"(b0), "r"(b1));
}

// ---------------- weight prepack (f16 fragment layout) ----------------
// logical B[mat] is 128(K) x 144(cols):
//  mat0: Win (128x128), cols 128..143 zero
//  mat1/2: hidden l: cols 0..127 = concat_h W_hid[l][h] (128x32),
//          128..131 = a_src heads, 132..135 = a_dst heads
//  mat3: cols 0..63 = W_out, col 64 = a_out_src, col 68 = a_out_dst
// frag layout (m16n8k16): g_B[mat][(step*18+tile)*64 + lane*2 + sel] = half2{
//   B[k][j], B[k+1][j] }  with k = step*16 + (lane&3)*2 + sel*8, j = tile*8 + (lane>>2)
__global__ void pack_kernel(const float* __restrict__ Win,
                            const float* __restrict__ a_hid,
                            const float* __restrict__ W_hid,
                            const float* __restrict__ a_out,
                            const float* __restrict__ W_out) {
    int idx = blockIdx.x * blockDim.x + threadIdx.x;
    if (idx >= 4 * 8 * 18 * 64) return;
    int sel  = idx & 1;
    int lane = (idx >> 1) & 31;
    int tile = (idx >> 6) % 18;
    int step = (idx / (18 * 64)) % 8;
    int mat  = idx / (8 * 18 * 64);
    int k = step * 16 + (lane & 3) * 2 + sel * 8;
    int j = tile * 8 + (lane >> 2);
    float v[2];
#pragma unroll
    for (int q = 0; q < 2; q++) {
        int kk = k + q;
        float val = 0.f;
        if (mat == 0) {
            if (j < 128) val = Win[kk * 128 + j];
        } else if (mat <= 2) {
            int l = mat - 1;
            if (j < 128) {
                int hd = j >> 5, jj = j & 31;
                val = W_hid[(((l * 4 + hd) * 128) + kk) * 32 + jj];
            } else if (j < 132) {
                val = a_hid[((l * 4 + (j - 128)) * 2 + 0) * 128 + kk];
            } else if (j < 136) {
                val = a_hid[((l * 4 + (j - 132)) * 2 + 1) * 128 + kk];
            }
        } else {
            if (j < 64) val = W_out[kk * 64 + j];
            else if (j == 64) val = a_out[kk];
            else if (j == 68) val = a_out[128 + kk];
        }
        v[q] = val;
    }
    __half2 h = __floats2half2_rn(v[0], v[1]);
    g_B[mat][(step * 18 + tile) * 64 + lane * 2 + sel] = *(uint32_t*)&h;
}

// ---------------- CSR build ----------------
__global__ void zero_deg_kernel() {
    int i = blockIdx.x * blockDim.x + threadIdx.x;
    if (i < NN) g_deg[i] = 0;
}
__global__ void count_deg_kernel(const int* __restrict__ ei) {
    int e = blockIdx.x * blockDim.x + threadIdx.x;
    if (e < EE) atomicAdd(&g_deg[ei[e]], 1);
}
__global__ void scan_partial_kernel() {
    __shared__ int sm[1024];
    int i = blockIdx.x * 1024 + threadIdx.x;
    sm[threadIdx.x] = (i < NN) ? g_deg[i] : 0;
    __syncthreads();
    for (int o = 512; o > 0; o >>= 1) {
        if (threadIdx.x < o) sm[threadIdx.x] += sm[threadIdx.x + o];
        __syncthreads();
    }
    if (threadIdx.x == 0) g_part[blockIdx.x] = sm[0];
}
__global__ void scan_off_kernel() {
    __shared__ int sm[128];
    int t = threadIdx.x;
    const int nch = (NN + 1023) / 1024;
    int mine = (t < nch) ? g_part[t] : 0;
    sm[t] = mine;
    __syncthreads();
    for (int o = 1; o < 128; o <<= 1) {
        int v = (t >= o) ? sm[t - o] : 0;
        __syncthreads();
        sm[t] += v;
        __syncthreads();
    }
    g_poff[t] = sm[t] - mine;
    if (t == 0) g_rp[NN] = EE;
}
__global__ void scan_apply_kernel() {
    __shared__ int sm[1024];
    int t = threadIdx.x;
    int i = blockIdx.x * 1024 + t;
    int v = (i < NN) ? g_deg[i] : 0;
    sm[t] = v;
    __syncthreads();
    for (int o = 1; o < 1024; o <<= 1) {
        int u = (t >= o) ? sm[t - o] : 0;
        __syncthreads();
        sm[t] += u;
        __syncthreads();
    }
    if (i < NN) {
        int ex = sm[t] - v + g_poff[blockIdx.x];
        g_rp[i] = ex;
        g_wp[i] = ex;
    }
}
__global__ void fill_csr_kernel(const int* __restrict__ ei) {
    int e = blockIdx.x * blockDim.x + threadIdx.x;
    if (e < EE) {
        int r = ei[e];
        int p = atomicAdd(&g_wp[r], 1);
        g_col[p] = ei[EE + e];
    }
}

// ---------------- fp16 tensor-core GEMM (m16n8k16) ----------------
// C[M,144] = A[M,128] @ B[128,144]. Block: 128 rows, 8 warps, warp = 16 rows x 144 cols.
#define GEMM_SMEM_BYTES (8 * 18 * 64 * 4)

template <bool AFP32, bool OUTHALF>
__global__ void __launch_bounds__(256, 2)
gemm_tc(const void* __restrict__ Aptr, const uint32_t* __restrict__ Bf,
        void* __restrict__ Cptr, float* __restrict__ Ss, float* __restrict__ Sd,
        const float* __restrict__ bias, int M, int nhw, int elu_out, int write_s) {
    extern __shared__ uint32_t Bs[];
    const int tid = threadIdx.x;
    {
        const uint4* src = (const uint4*)Bf;
        uint4* dst = (uint4*)Bs;
        for (int i = tid; i < 8 * 18 * 16; i += 256) dst[i] = src[i];
    }
    __syncthreads();

    const int warp = tid >> 5, lane = tid & 31;
    const int g = lane >> 2, tg = lane & 3;
    const int r0 = blockIdx.x * 128 + warp * 16 + g;
    const int r1 = r0 + 8;
    const bool v0 = r0 < M, v1 = r1 < M;

    float acc[18][4];
#pragma unroll
    for (int t = 0; t < 18; t++)
#pragma unroll
        for (int c = 0; c < 4; c++) acc[t][c] = 0.f;

#pragma unroll 2
    for (int step = 0; step < 8; step++) {
        const int k0 = step * 16 + tg * 2;
        uint32_t a0 = 0, a1 = 0, a2 = 0, a3 = 0;
        if (AFP32) {
            const float* A0 = (const float*)Aptr + (size_t)r0 * 128;
            const float* A1 = (const float*)Aptr + (size_t)r1 * 128;
            if (v0) {
                float2 f0 = *(const float2*)(A0 + k0);
                float2 f1 = *(const float2*)(A0 + k0 + 8);
                __half2 h0 = __floats2half2_rn(f0.x, f0.y);
                __half2 h1 = __floats2half2_rn(f1.x, f1.y);
                a0 = *(uint32_t*)&h0; a2 = *(uint32_t*)&h1;
            }
            if (v1) {
                float2 f0 = *(const float2*)(A1 + k0);
                float2 f1 = *(const float2*)(A1 + k0 + 8);
                __half2 h0 = __floats2half2_rn(f0.x, f0.y);
                __half2 h1 = __floats2half2_rn(f1.x, f1.y);
                a1 = *(uint32_t*)&h0; a3 = *(uint32_t*)&h1;
            }
        } else {
            const __half* A0 = (const __half*)Aptr + (size_t)r0 * 128;
            const __half* A1 = (const __half*)Aptr + (size_t)r1 * 128;
            if (v0) { a0 = *(const uint32_t*)(A0 + k0); a2 = *(const uint32_t*)(A0 + k0 + 8); }
            if (v1) { a1 = *(const uint32_t*)(A1 + k0); a3 = *(const uint32_t*)(A1 + k0 + 8); }
        }
        const uint32_t* bp = Bs + step * (18 * 64) + lane * 2;
#pragma unroll
        for (int t = 0; t < 18; t++) {
            uint2 b = *(const uint2*)(bp + t * 64);
            mma16(acc[t], a0, a1, a2, a3, b.x, b.y);
        }
    }

#pragma unroll
    for (int t = 0; t < 18; t++) {
        const int j = t * 8 + tg * 2;
        if (j < nhw) {
            float2 w0 = make_float2(acc[t][0], acc[t][1]);
            float2 w1 = make_float2(acc[t][2], acc[t][3]);
            if (bias) {
                float bx = bias[j], by = bias[j + 1];
                w0.x += bx; w0.y += by; w1.x += bx; w1.y += by;
            }
            if (elu_out) {
                w0.x = eluf(w0.x); w0.y = eluf(w0.y);
                w1.x = eluf(w1.x); w1.y = eluf(w1.y);
            }
            if (OUTHALF) {
                __half* C = (__half*)Cptr;
                if (v0) *(__half2*)(C + (size_t)r0 * nhw + j) = __floats2half2_rn(w0.x, w0.y);
                if (v1) *(__half2*)(C + (size_t)r1 * nhw + j) = __floats2half2_rn(w1.x, w1.y);
            } else {
                float* C = (float*)Cptr;
                if (v0) *(float2*)(C + (size_t)r0 * nhw + j) = w0;
                if (v1) *(float2*)(C + (size_t)r1 * nhw + j) = w1;
            }
        } else if (write_s) {
            const int d = j - nhw;
            if (d < 4) {
                if (v0) { Ss[r0 * 4 + d] = acc[t][0]; Ss[r0 * 4 + d + 1] = acc[t][1]; }
                if (v1) { Ss[r1 * 4 + d] = acc[t][2]; Ss[r1 * 4 + d + 1] = acc[t][3]; }
            } else if (d < 8) {
                if (v0) { Sd[r0 * 4 + d - 4] = acc[t][0]; Sd[r0 * 4 + d - 3] = acc[t][1]; }
                if (v1) { Sd[r1 * 4 + d - 4] = acc[t][2]; Sd[r1 * 4 + d - 3] = acc[t][3]; }
            }
        }
    }
}

// ---------------- aggregation: warp per node, two-phase chunked ----------------
// fp32 hw gather (round-3 known-best); output written as fp16 (feeds next GEMM).
__global__ void __launch_bounds__(256)
agg_hidden_kernel(__half* __restrict__ out) {
    __shared__ float4 s_w[8][32];
    __shared__ int    s_c[8][32];
    const int warp = threadIdx.x >> 5, lane = threadIdx.x & 31;
    const int node = blockIdx.x * 8 + warp;
    if (node >= NN) return;
    const int s = g_rp[node], e = g_rp[node + 1];
    uint2* op = (uint2*)(out + (size_t)node * 128);
    if (s == e) { op[lane] = make_uint2(0u, 0u); return; }
    const float4 as = ((const float4*)g_ss)[node];
    const int head = lane >> 3;

    // ---- pass 1: per-head max (logits of first 32 edges kept in regs) ----
    float l0 = -1e30f, l1 = -1e30f, l2 = -1e30f, l3 = -1e30f;
    int c0 = 0;
    const int my0 = s + lane;
    if (my0 < e) {
        c0 = g_col[my0];
        float4 sd = ((const float4*)g_sd)[c0];
        l0 = lreluf(as.x + sd.x); l1 = lreluf(as.y + sd.y);
        l2 = lreluf(as.z + sd.z); l3 = lreluf(as.w + sd.w);
    }
    float m0 = l0, m1 = l1, m2 = l2, m3 = l3;
    for (int ei = s + 32 + lane; ei < e; ei += 32) {
        int c = g_col[ei];
        float4 sd = ((const float4*)g_sd)[c];
        m0 = fmaxf(m0, lreluf(as.x + sd.x));
        m1 = fmaxf(m1, lreluf(as.y + sd.y));
        m2 = fmaxf(m2, lreluf(as.z + sd.z));
        m3 = fmaxf(m3, lreluf(as.w + sd.w));
    }
#pragma unroll
    for (int o = 16; o > 0; o >>= 1) {
        m0 = fmaxf(m0, __shfl_xor_sync(~0u, m0, o));
        m1 = fmaxf(m1, __shfl_xor_sync(~0u, m1, o));
        m2 = fmaxf(m2, __shfl_xor_sync(~0u, m2, o));
        m3 = fmaxf(m3, __shfl_xor_sync(~0u, m3, o));
    }

    // ---- pass 2: chunked weight + feature accumulation ----
    float4 acc = make_float4(0.f, 0.f, 0.f, 0.f);
    float sw0 = 0.f, sw1 = 0.f, sw2 = 0.f, sw3 = 0.f;
    for (int cs = s; cs < e; cs += 32) {
        const int my = cs + lane;
        float w0 = 0.f, w1 = 0.f, w2 = 0.f, w3 = 0.f;
        int c = 0;
        if (my < e) {
            if (cs == s) {
                c = c0;
                w0 = __expf(l0 - m0); w1 = __expf(l1 - m1);
                w2 = __expf(l2 - m2); w3 = __expf(l3 - m3);
            } else {
                c = g_col[my];
                float4 sd = ((const float4*)g_sd)[c];
                w0 = __expf(lreluf(as.x + sd.x) - m0);
                w1 = __expf(lreluf(as.y + sd.y) - m1);
                w2 = __expf(lreluf(as.z + sd.z) - m2);
                w3 = __expf(lreluf(as.w + sd.w) - m3);
            }
            sw0 += w0; sw1 += w1; sw2 += w2; sw3 += w3;
        }
        s_w[warp][lane] = make_float4(w0, w1, w2, w3);
        s_c[warp][lane] = c;
        __syncwarp();
        const int n = min(32, e - cs);
        for (int j = 0; j < n; j++) {
            const int cc = s_c[warp][j];
            const float w = ((const float*)&s_w[warp][j])[head];
            const float4 hr = ((const float4*)(g_hw + (size_t)cc * 128))[lane];
            acc.x += w * hr.x; acc.y += w * hr.y;
            acc.z += w * hr.z; acc.w += w * hr.w;
        }
        __syncwarp();
    }
#pragma unroll
    for (int o = 16; o > 0; o >>= 1) {
        sw0 += __shfl_xor_sync(~0u, sw0, o);
        sw1 += __shfl_xor_sync(~0u, sw1, o);
        sw2 += __shfl_xor_sync(~0u, sw2, o);
        sw3 += __shfl_xor_sync(~0u, sw3, o);
    }
    const float swh = (head == 0) ? sw0 : (head == 1) ? sw1 : (head == 2) ? sw2 : sw3;
    const float inv = __fdividef(1.f, swh);
    __half2 h0 = __floats2half2_rn(eluf(acc.x * inv), eluf(acc.y * inv));
    __half2 h1 = __floats2half2_rn(eluf(acc.z * inv), eluf(acc.w * inv));
    op[lane] = make_uint2(*(uint32_t*)&h0, *(uint32_t*)&h1);
}

// final: 1 head, 64 dims; lane owns dims 2l..2l+1 (fp32 output).
__global__ void __launch_bounds__(256)
agg_final_kernel(float* __restrict__ out) {
    __shared__ float s_w[8][32];
    __shared__ int   s_c[8][32];
    const int warp = threadIdx.x >> 5, lane = threadIdx.x & 31;
    const int node = blockIdx.x * 8 + warp;
    if (node >= NN) return;
    const int s = g_rp[node], e = g_rp[node + 1];
    float2* op = (float2*)(out + (size_t)node * 64);
    if (s == e) { op[lane] = make_float2(0.f, 0.f); return; }
    const float as = g_ss[node * 4];

    float l0 = -1e30f;
    int c0 = 0;
    const int my0 = s + lane;
    if (my0 < e) { c0 = g_col[my0]; l0 = lreluf(as + g_sd[c0 * 4]); }
    float mm = l0;
    for (int ei = s + 32 + lane; ei < e; ei += 32)
        mm = fmaxf(mm, lreluf(as + g_sd[g_col[ei] * 4]));
#pragma unroll
    for (int o = 16; o > 0; o >>= 1) mm = fmaxf(mm, __shfl_xor_sync(~0u, mm, o));

    float2 acc = make_float2(0.f, 0.f);
    float sw = 0.f;
    for (int cs = s; cs < e; cs += 32) {
        const int my = cs + lane;
        float w = 0.f;
        int c = 0;
        if (my < e) {
            if (cs == s) { c = c0; w = __expf(l0 - mm); }
            else { c = g_col[my]; w = __expf(lreluf(as + g_sd[c * 4]) - mm); }
            sw += w;
        }
        s_w[warp][lane] = w;
        s_c[warp][lane] = c;
        __syncwarp();
        const int n = min(32, e - cs);
        for (int j = 0; j < n; j++) {
            const int cc = s_c[warp][j];
            const float w2 = s_w[warp][j];
            const float2 hr = ((const float2*)(g_hw + (size_t)cc * 64))[lane];
            acc.x += w2 * hr.x; acc.y += w2 * hr.y;
        }
        __syncwarp();
    }
#pragma unroll
    for (int o = 16; o > 0; o >>= 1) sw += __shfl_xor_sync(~0u, sw, o);
    const float inv = __fdividef(1.f, sw);
    op[lane] = make_float2(acc.x * inv, acc.y * inv);
}

// ---------------- launch ----------------
extern "C" void kernel_launch(void* const* d_in, const int* in_sizes, int n_in,
                              void* d_out, int out_size) {
    const float* x     = (const float*)d_in[0];
    const int*   ei    = (const int*)d_in[1];
    const float* Win   = (const float*)d_in[2];
    const float* b_in  = (const float*)d_in[3];
    const float* a_hid = (const float*)d_in[4];
    const float* W_hid = (const float*)d_in[5];
    const float* a_out = (const float*)d_in[6];
    const float* W_out = (const float*)d_in[7];
    float* out = (float*)d_out;
    (void)in_sizes; (void)n_in; (void)out_size;

    cudaFuncSetAttribute(gemm_tc<true, true>, cudaFuncAttributeMaxDynamicSharedMemorySize,
                         GEMM_SMEM_BYTES);
    cudaFuncSetAttribute(gemm_tc<false, false>, cudaFuncAttributeMaxDynamicSharedMemorySize,
                         GEMM_SMEM_BYTES);

    __half* pre;
    float *hw, *ss, *sd;
    uint32_t* bbase;
    cudaGetSymbolAddress((void**)&pre, g_pre);
    cudaGetSymbolAddress((void**)&hw, g_hw);
    cudaGetSymbolAddress((void**)&ss, g_ss);
    cudaGetSymbolAddress((void**)&sd, g_sd);
    cudaGetSymbolAddress((void**)&bbase, g_B);
    uint32_t* B0 = bbase;
    uint32_t* B1 = bbase + 8 * 18 * 64;
    uint32_t* B2 = bbase + 2 * 8 * 18 * 64;
    uint32_t* B3 = bbase + 3 * 8 * 18 * 64;

    pack_kernel<<<(4 * 8 * 18 * 64 + 255) / 256, 256>>>(Win, a_hid, W_hid, a_out, W_out);
    zero_deg_kernel<<<(NN + 255) / 256, 256>>>();
    count_deg_kernel<<<(EE + 255) / 256, 256>>>(ei);
    scan_partial_kernel<<<(NN + 1023) / 1024, 1024>>>();
    scan_off_kernel<<<1, 128>>>();
    scan_apply_kernel<<<(NN + 1023) / 1024, 1024>>>();
    fill_csr_kernel<<<(EE + 255) / 256, 256>>>(ei);

    const int gx = (NN + 127) / 128;
    const int ga = (NN + 7) / 8;

    // input linear: pre = elu(x @ Win + b_in)   (A fp32 -> cvt, out fp16)
    gemm_tc<true, true><<<gx, 256, GEMM_SMEM_BYTES>>>(x, B0, pre, nullptr, nullptr, b_in, NN, 128, 1, 0);
    // hidden layer 1
    gemm_tc<false, false><<<gx, 256, GEMM_SMEM_BYTES>>>(pre, B1, hw, ss, sd, nullptr, NN, 128, 0, 1);
    agg_hidden_kernel<<<ga, 256>>>(pre);
    // hidden layer 2
    gemm_tc<false, false><<<gx, 256, GEMM_SMEM_BYTES>>>(pre, B2, hw, ss, sd, nullptr, NN, 128, 0, 1);
    agg_hidden_kernel<<<ga, 256>>>(pre);
    // output layer
    gemm_tc<false, false><<<gx, 256, GEMM_SMEM_BYTES>>>(pre, B3, hw, ss, sd, nullptr, NN, 64, 0, 1);
    agg_final_kernel<<<ga, 256>>>(out);
}

// round 6
// speedup vs baseline: 1.3037x; 1.0616x over previous
#include <cuda_runtime.h>
#include <cuda_fp16.h>
#include <cstdint>
#include <cstdio>

#define NN 100000
#define EE 1600000
#define BSTRIDE (8 * 17 * 64)

// ---------------- device scratch (no allocations allowed) ----------------
__device__ uint32_t g_B[4][BSTRIDE];             // prepacked weights, f16 mma fragment layout
__device__ __half   g_pre[(size_t)NN * 128];     // post-ELU h (fp16: feeds GEMM A)
__device__ float    g_hw[(size_t)NN * 128];      // h @ W (projected values, fp32)
__device__ float    g_ss[NN * 4];                // s_src per head
__device__ float    g_sd[NN * 4];                // s_dst per head
__device__ int      g_deg[NN];
__device__ int      g_rp[NN + 1];                // CSR row_ptr (by edge_index[0])
__device__ int      g_wp[NN];
__device__ int      g_col[EE];                   // CSR col values
__device__ int      g_part[128];
__device__ int      g_poff[128];

// ---------------- helpers ----------------
__device__ __forceinline__ float eluf(float x) { return x > 0.f ? x : expm1f(x); }
__device__ __forceinline__ float lreluf(float x) { return fmaxf(x, 0.2f * x); }
__device__ __forceinline__ void mma16(float* c, uint32_t a0, uint32_t a1, uint32_t a2,
                                      uint32_t a3, uint32_t b0, uint32_t b1) {
    asm("mma.sync.aligned.m16n8k16.row.col.f32.f16.f16.f32 "
        "{%0,%1,%2,%3}, {%4,%5,%6,%7}, {%8,%9}, {%0,%1,%2,%3};"
        : "+f"(c[0]), "+f"(c[1]), "+f"(c[2]), "+f"(c[3])
        : "r"(a0), "r"(a1), "r"(a2), "r"(a3), "r"(b0), "r"(b1));
}

__constant__ int c_NT[4] = {16, 17, 17, 9};

// ---------------- weight prepack (f16 fragment layout, per-mat tile count) ----------------
// logical B[mat] is 128(K) x cols:
//  mat0 (NT=16): Win (128x128)
//  mat1/2 (NT=17): cols 0..127 = concat_h W_hid[l][h], 128..131 = a_src, 132..135 = a_dst
//  mat3 (NT=9): cols 0..63 = W_out, col 64 = a_out_src, col 68 = a_out_dst
// frag layout (m16n8k16): g_B[mat][(step*NT+tile)*64 + lane*2 + sel] = half2{
//   B[k][j], B[k+1][j] }  with k = step*16 + (lane&3)*2 + sel*8, j = tile*8 + (lane>>2)
__global__ void pack_kernel(const float* __restrict__ Win,
                            const float* __restrict__ a_hid,
                            const float* __restrict__ W_hid,
                            const float* __restrict__ a_out,
                            const float* __restrict__ W_out) {
    int idx = blockIdx.x * blockDim.x + threadIdx.x;
    if (idx >= 4 * 8 * 17 * 64) return;
    int sel  = idx & 1;
    int lane = (idx >> 1) & 31;
    int tile = (idx >> 6) % 17;
    int step = (idx / (17 * 64)) % 8;
    int mat  = idx / (8 * 17 * 64);
    const int NT = c_NT[mat];
    if (tile >= NT) return;
    int k = step * 16 + (lane & 3) * 2 + sel * 8;
    int j = tile * 8 + (lane >> 2);
    float v[2];
#pragma unroll
    for (int q = 0; q < 2; q++) {
        int kk = k + q;
        float val = 0.f;
        if (mat == 0) {
            if (j < 128) val = Win[kk * 128 + j];
        } else if (mat <= 2) {
            int l = mat - 1;
            if (j < 128) {
                int hd = j >> 5, jj = j & 31;
                val = W_hid[(((l * 4 + hd) * 128) + kk) * 32 + jj];
            } else if (j < 132) {
                val = a_hid[((l * 4 + (j - 128)) * 2 + 0) * 128 + kk];
            } else if (j < 136) {
                val = a_hid[((l * 4 + (j - 132)) * 2 + 1) * 128 + kk];
            }
        } else {
            if (j < 64) val = W_out[kk * 64 + j];
            else if (j == 64) val = a_out[kk];
            else if (j == 68) val = a_out[128 + kk];
        }
        v[q] = val;
    }
    __half2 h = __floats2half2_rn(v[0], v[1]);
    g_B[mat][(step * NT + tile) * 64 + lane * 2 + sel] = *(uint32_t*)&h;
}

// ---------------- CSR build ----------------
__global__ void zero_deg_kernel() {
    int i = blockIdx.x * blockDim.x + threadIdx.x;
    if (i < NN) g_deg[i] = 0;
}
__global__ void count_deg_kernel(const int* __restrict__ ei) {
    int e = blockIdx.x * blockDim.x + threadIdx.x;
    if (e < EE) atomicAdd(&g_deg[ei[e]], 1);
}
__global__ void scan_partial_kernel() {
    __shared__ int sm[1024];
    int i = blockIdx.x * 1024 + threadIdx.x;
    sm[threadIdx.x] = (i < NN) ? g_deg[i] : 0;
    __syncthreads();
    for (int o = 512; o > 0; o >>= 1) {
        if (threadIdx.x < o) sm[threadIdx.x] += sm[threadIdx.x + o];
        __syncthreads();
    }
    if (threadIdx.x == 0) g_part[blockIdx.x] = sm[0];
}
__global__ void scan_off_kernel() {
    __shared__ int sm[128];
    int t = threadIdx.x;
    const int nch = (NN + 1023) / 1024;
    int mine = (t < nch) ? g_part[t] : 0;
    sm[t] = mine;
    __syncthreads();
    for (int o = 1; o < 128; o <<= 1) {
        int v = (t >= o) ? sm[t - o] : 0;
        __syncthreads();
        sm[t] += v;
        __syncthreads();
    }
    g_poff[t] = sm[t] - mine;
    if (t == 0) g_rp[NN] = EE;
}
__global__ void scan_apply_kernel() {
    __shared__ int sm[1024];
    int t = threadIdx.x;
    int i = blockIdx.x * 1024 + t;
    int v = (i < NN) ? g_deg[i] : 0;
    sm[t] = v;
    __syncthreads();
    for (int o = 1; o < 1024; o <<= 1) {
        int u = (t >= o) ? sm[t - o] : 0;
        __syncthreads();
        sm[t] += u;
        __syncthreads();
    }
    if (i < NN) {
        int ex = sm[t] - v + g_poff[blockIdx.x];
        g_rp[i] = ex;
        g_wp[i] = ex;
    }
}
__global__ void fill_csr_kernel(const int* __restrict__ ei) {
    int e = blockIdx.x * blockDim.x + threadIdx.x;
    if (e < EE) {
        int r = ei[e];
        int p = atomicAdd(&g_wp[r], 1);
        g_col[p] = ei[EE + e];
    }
}

// ---------------- fp16 tensor-core GEMM (m16n8k16), NT n-tiles ----------------
template <int NT, bool AFP32, bool OUTHALF>
__global__ void __launch_bounds__(256, 2)
gemm_tc(const void* __restrict__ Aptr, const uint32_t* __restrict__ Bf,
        void* __restrict__ Cptr, float* __restrict__ Ss, float* __restrict__ Sd,
        const float* __restrict__ bias, int M, int nhw, int elu_out, int write_s) {
    extern __shared__ uint32_t Bs[];
    const int tid = threadIdx.x;
    {
        const uint4* src = (const uint4*)Bf;
        uint4* dst = (uint4*)Bs;
        for (int i = tid; i < 8 * NT * 16; i += 256) dst[i] = src[i];
    }
    __syncthreads();

    const int warp = tid >> 5, lane = tid & 31;
    const int g = lane >> 2, tg = lane & 3;
    const int r0 = blockIdx.x * 128 + warp * 16 + g;
    const int r1 = r0 + 8;
    const bool v0 = r0 < M, v1 = r1 < M;

    float acc[NT][4];
#pragma unroll
    for (int t = 0; t < NT; t++)
#pragma unroll
        for (int c = 0; c < 4; c++) acc[t][c] = 0.f;

#pragma unroll 2
    for (int step = 0; step < 8; step++) {
        const int k0 = step * 16 + tg * 2;
        uint32_t a0 = 0, a1 = 0, a2 = 0, a3 = 0;
        if (AFP32) {
            const float* A0 = (const float*)Aptr + (size_t)r0 * 128;
            const float* A1 = (const float*)Aptr + (size_t)r1 * 128;
            if (v0) {
                float2 f0 = *(const float2*)(A0 + k0);
                float2 f1 = *(const float2*)(A0 + k0 + 8);
                __half2 h0 = __floats2half2_rn(f0.x, f0.y);
                __half2 h1 = __floats2half2_rn(f1.x, f1.y);
                a0 = *(uint32_t*)&h0; a2 = *(uint32_t*)&h1;
            }
            if (v1) {
                float2 f0 = *(const float2*)(A1 + k0);
                float2 f1 = *(const float2*)(A1 + k0 + 8);
                __half2 h0 = __floats2half2_rn(f0.x, f0.y);
                __half2 h1 = __floats2half2_rn(f1.x, f1.y);
                a1 = *(uint32_t*)&h0; a3 = *(uint32_t*)&h1;
            }
        } else {
            const __half* A0 = (const __half*)Aptr + (size_t)r0 * 128;
            const __half* A1 = (const __half*)Aptr + (size_t)r1 * 128;
            if (v0) { a0 = *(const uint32_t*)(A0 + k0); a2 = *(const uint32_t*)(A0 + k0 + 8); }
            if (v1) { a1 = *(const uint32_t*)(A1 + k0); a3 = *(const uint32_t*)(A1 + k0 + 8); }
        }
        const uint32_t* bp = Bs + step * (NT * 64) + lane * 2;
#pragma unroll
        for (int t = 0; t < NT; t++) {
            uint2 b = *(const uint2*)(bp + t * 64);
            mma16(acc[t], a0, a1, a2, a3, b.x, b.y);
        }
    }

#pragma unroll
    for (int t = 0; t < NT; t++) {
        const int j = t * 8 + tg * 2;
        if (j < nhw) {
            float2 w0 = make_float2(acc[t][0], acc[t][1]);
            float2 w1 = make_float2(acc[t][2], acc[t][3]);
            if (bias) {
                float bx = bias[j], by = bias[j + 1];
                w0.x += bx; w0.y += by; w1.x += bx; w1.y += by;
            }
            if (elu_out) {
                w0.x = eluf(w0.x); w0.y = eluf(w0.y);
                w1.x = eluf(w1.x); w1.y = eluf(w1.y);
            }
            if (OUTHALF) {
                __half* C = (__half*)Cptr;
                if (v0) *(__half2*)(C + (size_t)r0 * nhw + j) = __floats2half2_rn(w0.x, w0.y);
                if (v1) *(__half2*)(C + (size_t)r1 * nhw + j) = __floats2half2_rn(w1.x, w1.y);
            } else {
                float* C = (float*)Cptr;
                if (v0) *(float2*)(C + (size_t)r0 * nhw + j) = w0;
                if (v1) *(float2*)(C + (size_t)r1 * nhw + j) = w1;
            }
        } else if (write_s) {
            const int d = j - nhw;
            if (d < 4) {
                if (v0) { Ss[r0 * 4 + d] = acc[t][0]; Ss[r0 * 4 + d + 1] = acc[t][1]; }
                if (v1) { Ss[r1 * 4 + d] = acc[t][2]; Ss[r1 * 4 + d + 1] = acc[t][3]; }
            } else if (d < 8) {
                if (v0) { Sd[r0 * 4 + d - 4] = acc[t][0]; Sd[r0 * 4 + d - 3] = acc[t][1]; }
                if (v1) { Sd[r1 * 4 + d - 4] = acc[t][2]; Sd[r1 * 4 + d - 3] = acc[t][3]; }
            }
        }
    }
}

// ---------------- aggregation: warp per node, two-phase chunked ----------------
__global__ void __launch_bounds__(256)
agg_hidden_kernel(__half* __restrict__ out) {
    __shared__ float4 s_w[8][32];
    __shared__ int    s_c[8][32];
    const int warp = threadIdx.x >> 5, lane = threadIdx.x & 31;
    const int node = blockIdx.x * 8 + warp;
    if (node >= NN) return;
    const int s = g_rp[node], e = g_rp[node + 1];
    uint2* op = (uint2*)(out + (size_t)node * 128);
    if (s == e) { op[lane] = make_uint2(0u, 0u); return; }
    const float4 as = ((const float4*)g_ss)[node];
    const int head = lane >> 3;

    float l0 = -1e30f, l1 = -1e30f, l2 = -1e30f, l3 = -1e30f;
    int c0 = 0;
    const int my0 = s + lane;
    if (my0 < e) {
        c0 = g_col[my0];
        float4 sd = ((const float4*)g_sd)[c0];
        l0 = lreluf(as.x + sd.x); l1 = lreluf(as.y + sd.y);
        l2 = lreluf(as.z + sd.z); l3 = lreluf(as.w + sd.w);
    }
    float m0 = l0, m1 = l1, m2 = l2, m3 = l3;
    for (int ei = s + 32 + lane; ei < e; ei += 32) {
        int c = g_col[ei];
        float4 sd = ((const float4*)g_sd)[c];
        m0 = fmaxf(m0, lreluf(as.x + sd.x));
        m1 = fmaxf(m1, lreluf(as.y + sd.y));
        m2 = fmaxf(m2, lreluf(as.z + sd.z));
        m3 = fmaxf(m3, lreluf(as.w + sd.w));
    }
#pragma unroll
    for (int o = 16; o > 0; o >>= 1) {
        m0 = fmaxf(m0, __shfl_xor_sync(~0u, m0, o));
        m1 = fmaxf(m1, __shfl_xor_sync(~0u, m1, o));
        m2 = fmaxf(m2, __shfl_xor_sync(~0u, m2, o));
        m3 = fmaxf(m3, __shfl_xor_sync(~0u, m3, o));
    }

    float4 acc = make_float4(0.f, 0.f, 0.f, 0.f);
    float sw0 = 0.f, sw1 = 0.f, sw2 = 0.f, sw3 = 0.f;
    for (int cs = s; cs < e; cs += 32) {
        const int my = cs + lane;
        float w0 = 0.f, w1 = 0.f, w2 = 0.f, w3 = 0.f;
        int c = 0;
        if (my < e) {
            if (cs == s) {
                c = c0;
                w0 = __expf(l0 - m0); w1 = __expf(l1 - m1);
                w2 = __expf(l2 - m2); w3 = __expf(l3 - m3);
            } else {
                c = g_col[my];
                float4 sd = ((const float4*)g_sd)[c];
                w0 = __expf(lreluf(as.x + sd.x) - m0);
                w1 = __expf(lreluf(as.y + sd.y) - m1);
                w2 = __expf(lreluf(as.z + sd.z) - m2);
                w3 = __expf(lreluf(as.w + sd.w) - m3);
            }
            sw0 += w0; sw1 += w1; sw2 += w2; sw3 += w3;
        }
        s_w[warp][lane] = make_float4(w0, w1, w2, w3);
        s_c[warp][lane] = c;
        __syncwarp();
        const int n = min(32, e - cs);
        for (int j = 0; j < n; j++) {
            const int cc = s_c[warp][j];
            const float w = ((const float*)&s_w[warp][j])[head];
            const float4 hr = ((const float4*)(g_hw + (size_t)cc * 128))[lane];
            acc.x += w * hr.x; acc.y += w * hr.y;
            acc.z += w * hr.z; acc.w += w * hr.w;
        }
        __syncwarp();
    }
#pragma unroll
    for (int o = 16; o > 0; o >>= 1) {
        sw0 += __shfl_xor_sync(~0u, sw0, o);
        sw1 += __shfl_xor_sync(~0u, sw1, o);
        sw2 += __shfl_xor_sync(~0u, sw2, o);
        sw3 += __shfl_xor_sync(~0u, sw3, o);
    }
    const float swh = (head == 0) ? sw0 : (head == 1) ? sw1 : (head == 2) ? sw2 : sw3;
    const float inv = __fdividef(1.f, swh);
    __half2 h0 = __floats2half2_rn(eluf(acc.x * inv), eluf(acc.y * inv));
    __half2 h1 = __floats2half2_rn(eluf(acc.z * inv), eluf(acc.w * inv));
    op[lane] = make_uint2(*(uint32_t*)&h0, *(uint32_t*)&h1);
}

__global__ void __launch_bounds__(256)
agg_final_kernel(float* __restrict__ out) {
    __shared__ float s_w[8][32];
    __shared__ int   s_c[8][32];
    const int warp = threadIdx.x >> 5, lane = threadIdx.x & 31;
    const int node = blockIdx.x * 8 + warp;
    if (node >= NN) return;
    const int s = g_rp[node], e = g_rp[node + 1];
    float2* op = (float2*)(out + (size_t)node * 64);
    if (s == e) { op[lane] = make_float2(0.f, 0.f); return; }
    const float as = g_ss[node * 4];

    float l0 = -1e30f;
    int c0 = 0;
    const int my0 = s + lane;
    if (my0 < e) { c0 = g_col[my0]; l0 = lreluf(as + g_sd[c0 * 4]); }
    float mm = l0;
    for (int ei = s + 32 + lane; ei < e; ei += 32)
        mm = fmaxf(mm, lreluf(as + g_sd[g_col[ei] * 4]));
#pragma unroll
    for (int o = 16; o > 0; o >>= 1) mm = fmaxf(mm, __shfl_xor_sync(~0u, mm, o));

    float2 acc = make_float2(0.f, 0.f);
    float sw = 0.f;
    for (int cs = s; cs < e; cs += 32) {
        const int my = cs + lane;
        float w = 0.f;
        int c = 0;
        if (my < e) {
            if (cs == s) { c = c0; w = __expf(l0 - mm); }
            else { c = g_col[my]; w = __expf(lreluf(as + g_sd[c * 4]) - mm); }
            sw += w;
        }
        s_w[warp][lane] = w;
        s_c[warp][lane] = c;
        __syncwarp();
        const int n = min(32, e - cs);
        for (int j = 0; j < n; j++) {
            const int cc = s_c[warp][j];
            const float w2 = s_w[warp][j];
            const float2 hr = ((const float2*)(g_hw + (size_t)cc * 64))[lane];
            acc.x += w2 * hr.x; acc.y += w2 * hr.y;
        }
        __syncwarp();
    }
#pragma unroll
    for (int o = 16; o > 0; o >>= 1) sw += __shfl_xor_sync(~0u, sw, o);
    const float inv = __fdividef(1.f, sw);
    op[lane] = make_float2(acc.x * inv, acc.y * inv);
}

// ---------------- launch ----------------
extern "C" void kernel_launch(void* const* d_in, const int* in_sizes, int n_in,
                              void* d_out, int out_size) {
    const float* x     = (const float*)d_in[0];
    const int*   ei    = (const int*)d_in[1];
    const float* Win   = (const float*)d_in[2];
    const float* b_in  = (const float*)d_in[3];
    const float* a_hid = (const float*)d_in[4];
    const float* W_hid = (const float*)d_in[5];
    const float* a_out = (const float*)d_in[6];
    const float* W_out = (const float*)d_in[7];
    float* out = (float*)d_out;
    (void)in_sizes; (void)n_in; (void)out_size;

    // one-time resource setup (host objects only; no device memory)
    static cudaStream_t s2 = nullptr;
    static cudaEvent_t evA = nullptr, evB = nullptr;
    static bool inited = false;
    if (!inited) {
        cudaStreamCreateWithFlags(&s2, cudaStreamNonBlocking);
        cudaEventCreateWithFlags(&evA, cudaEventDisableTiming);
        cudaEventCreateWithFlags(&evB, cudaEventDisableTiming);
        cudaFuncSetAttribute(gemm_tc<16, true, true>,
                             cudaFuncAttributeMaxDynamicSharedMemorySize, 8 * 16 * 64 * 4);
        cudaFuncSetAttribute(gemm_tc<17, false, false>,
                             cudaFuncAttributeMaxDynamicSharedMemorySize, 8 * 17 * 64 * 4);
        cudaFuncSetAttribute(gemm_tc<9, false, false>,
                             cudaFuncAttributeMaxDynamicSharedMemorySize, 8 * 9 * 64 * 4);
        inited = true;
    }

    __half* pre;
    float *hw, *ss, *sd;
    uint32_t* bbase;
    cudaGetSymbolAddress((void**)&pre, g_pre);
    cudaGetSymbolAddress((void**)&hw, g_hw);
    cudaGetSymbolAddress((void**)&ss, g_ss);
    cudaGetSymbolAddress((void**)&sd, g_sd);
    cudaGetSymbolAddress((void**)&bbase, g_B);
    uint32_t* B0 = bbase;
    uint32_t* B1 = bbase + BSTRIDE;
    uint32_t* B2 = bbase + 2 * BSTRIDE;
    uint32_t* B3 = bbase + 3 * BSTRIDE;

    const int gx = (NN + 127) / 128;
    const int ga = (NN + 7) / 8;

    // fork: CSR build on s2, weight pack + first two GEMMs on main stream
    cudaEventRecord(evA, 0);
    cudaStreamWaitEvent(s2, evA, 0);
    zero_deg_kernel<<<(NN + 255) / 256, 256, 0, s2>>>();
    count_deg_kernel<<<(EE + 255) / 256, 256, 0, s2>>>(ei);
    scan_partial_kernel<<<(NN + 1023) / 1024, 1024, 0, s2>>>();
    scan_off_kernel<<<1, 128, 0, s2>>>();
    scan_apply_kernel<<<(NN + 1023) / 1024, 1024, 0, s2>>>();
    fill_csr_kernel<<<(EE + 255) / 256, 256, 0, s2>>>(ei);
    cudaEventRecord(evB, s2);

    pack_kernel<<<(4 * 8 * 17 * 64 + 255) / 256, 256>>>(Win, a_hid, W_hid, a_out, W_out);
    // input linear: pre = elu(x @ Win + b_in)
    gemm_tc<16, true, true><<<gx, 256, 8 * 16 * 64 * 4>>>(x, B0, pre, nullptr, nullptr, b_in, NN, 128, 1, 0);
    // hidden layer 1 projection + scores (independent of CSR)
    gemm_tc<17, false, false><<<gx, 256, 8 * 17 * 64 * 4>>>(pre, B1, hw, ss, sd, nullptr, NN, 128, 0, 1);

    // join: aggregation needs the CSR
    cudaStreamWaitEvent(0, evB, 0);
    agg_hidden_kernel<<<ga, 256>>>(pre);
    // hidden layer 2
    gemm_tc<17, false, false><<<gx, 256, 8 * 17 * 64 * 4>>>(pre, B2, hw, ss, sd, nullptr, NN, 128, 0, 1);
    agg_hidden_kernel<<<ga, 256>>>(pre);
    // output layer
    gemm_tc<9, false, false><<<gx, 256, 8 * 9 * 64 * 4>>>(pre, B3, hw, ss, sd, nullptr, NN, 64, 0, 1);
    agg_final_kernel<<<ga, 256>>>(out);
}

// round 7
// speedup vs baseline: 1.3049x; 1.0009x over previous
#include <cuda_runtime.h>
#include <cuda_fp16.h>
#include <cstdint>
#include <cstdio>

#define NN 100000
#define EE 1600000
#define BSTRIDE (8 * 17 * 64)

// ---------------- device scratch (no allocations allowed) ----------------
__device__ uint32_t g_B[4][BSTRIDE];             // prepacked weights, f16 mma fragment layout
__device__ __half   g_pre[(size_t)NN * 128];     // post-ELU h (fp16: feeds GEMM A)
__device__ float    g_hw[(size_t)NN * 128];      // h @ W (projected values, fp32)
__device__ float    g_ss[NN * 4];                // s_src per head
__device__ float    g_sd[NN * 4];                // s_dst per head
__device__ int      g_deg[NN];                   // zero at entry; re-zeroed by scan_apply
__device__ int      g_rp[NN + 1];                // CSR row_ptr (by edge_index[0])
__device__ int      g_wp[NN];
__device__ int      g_col[EE];                   // CSR col values
__device__ int      g_part[128];

// ---------------- helpers ----------------
__device__ __forceinline__ float eluf(float x) { return x > 0.f ? x : expm1f(x); }
__device__ __forceinline__ float lreluf(float x) { return fmaxf(x, 0.2f * x); }
__device__ __forceinline__ void mma16(float* c, uint32_t a0, uint32_t a1, uint32_t a2,
                                      uint32_t a3, uint32_t b0, uint32_t b1) {
    asm("mma.sync.aligned.m16n8k16.row.col.f32.f16.f16.f32 "
        "{%0,%1,%2,%3}, {%4,%5,%6,%7}, {%8,%9}, {%0,%1,%2,%3};"
        : "+f"(c[0]), "+f"(c[1]), "+f"(c[2]), "+f"(c[3])
        : "r"(a0), "r"(a1), "r"(a2), "r"(a3), "r"(b0), "r"(b1));
}

__constant__ int c_NT[4] = {16, 17, 17, 9};

// ---------------- weight prepack (f16 fragment layout, per-mat tile count) ----------------
__global__ void pack_kernel(const float* __restrict__ Win,
                            const float* __restrict__ a_hid,
                            const float* __restrict__ W_hid,
                            const float* __restrict__ a_out,
                            const float* __restrict__ W_out) {
    int idx = blockIdx.x * blockDim.x + threadIdx.x;
    if (idx >= 4 * 8 * 17 * 64) return;
    int sel  = idx & 1;
    int lane = (idx >> 1) & 31;
    int tile = (idx >> 6) % 17;
    int step = (idx / (17 * 64)) % 8;
    int mat  = idx / (8 * 17 * 64);
    const int NT = c_NT[mat];
    if (tile >= NT) return;
    int k = step * 16 + (lane & 3) * 2 + sel * 8;
    int j = tile * 8 + (lane >> 2);
    float v[2];
#pragma unroll
    for (int q = 0; q < 2; q++) {
        int kk = k + q;
        float val = 0.f;
        if (mat == 0) {
            if (j < 128) val = Win[kk * 128 + j];
        } else if (mat <= 2) {
            int l = mat - 1;
            if (j < 128) {
                int hd = j >> 5, jj = j & 31;
                val = W_hid[(((l * 4 + hd) * 128) + kk) * 32 + jj];
            } else if (j < 132) {
                val = a_hid[((l * 4 + (j - 128)) * 2 + 0) * 128 + kk];
            } else if (j < 136) {
                val = a_hid[((l * 4 + (j - 132)) * 2 + 1) * 128 + kk];
            }
        } else {
            if (j < 64) val = W_out[kk * 64 + j];
            else if (j == 64) val = a_out[kk];
            else if (j == 68) val = a_out[128 + kk];
        }
        v[q] = val;
    }
    __half2 h = __floats2half2_rn(v[0], v[1]);
    g_B[mat][(step * NT + tile) * 64 + lane * 2 + sel] = *(uint32_t*)&h;
}

// ---------------- CSR build (4 kernels) ----------------
// invariant: g_deg is all-zero on entry to count_deg (zero-initialized at module
// load; scan_apply re-zeroes it after consumption on every run).
__global__ void count_deg_kernel(const int* __restrict__ ei) {
    int e = blockIdx.x * blockDim.x + threadIdx.x;
    if (e < EE) atomicAdd(&g_deg[ei[e]], 1);
}
__global__ void scan_partial_kernel() {  // grid=98, block=1024
    __shared__ int sm[1024];
    int i = blockIdx.x * 1024 + threadIdx.x;
    sm[threadIdx.x] = (i < NN) ? g_deg[i] : 0;
    __syncthreads();
    for (int o = 512; o > 0; o >>= 1) {
        if (threadIdx.x < o) sm[threadIdx.x] += sm[threadIdx.x + o];
        __syncthreads();
    }
    if (threadIdx.x == 0) g_part[blockIdx.x] = sm[0];
}
// fused: per-block offset from inline scan of partials + local scan + deg re-zero
__global__ void scan_apply_kernel() {  // grid=98, block=1024
    __shared__ int sp[128];
    __shared__ int sm[1024];
    const int t = threadIdx.x;
    const int nch = (NN + 1023) / 1024;   // 98
    if (t < 128) sp[t] = (t < nch) ? g_part[t] : 0;
    __syncthreads();
    for (int o = 1; o < 128; o <<= 1) {
        int v = (t >= o && t < 128) ? sp[t - o] : 0;
        __syncthreads();
        if (t < 128) sp[t] += v;
        __syncthreads();
    }
    const int boff = sp[blockIdx.x] - g_part[blockIdx.x];  // exclusive offset

    const int i = blockIdx.x * 1024 + t;
    const int v = (i < NN) ? g_deg[i] : 0;
    sm[t] = v;
    __syncthreads();
    for (int o = 1; o < 1024; o <<= 1) {
        int u = (t >= o) ? sm[t - o] : 0;
        __syncthreads();
        sm[t] += u;
        __syncthreads();
    }
    if (i < NN) {
        int ex = sm[t] - v + boff;
        g_rp[i] = ex;
        g_wp[i] = ex;
        g_deg[i] = 0;   // restore invariant for next run
    }
    if (blockIdx.x == 0 && t == 0) g_rp[NN] = EE;
}
__global__ void fill_csr_kernel(const int* __restrict__ ei) {
    int e = blockIdx.x * blockDim.x + threadIdx.x;
    if (e < EE) {
        int r = ei[e];
        int p = atomicAdd(&g_wp[r], 1);
        g_col[p] = ei[EE + e];
    }
}

// ---------------- fp16 tensor-core GEMM (m16n8k16), NT n-tiles ----------------
template <int NT, bool AFP32, bool OUTHALF>
__global__ void __launch_bounds__(256, 2)
gemm_tc(const void* __restrict__ Aptr, const uint32_t* __restrict__ Bf,
        void* __restrict__ Cptr, float* __restrict__ Ss, float* __restrict__ Sd,
        const float* __restrict__ bias, int M, int nhw, int elu_out, int write_s) {
    extern __shared__ uint32_t Bs[];
    const int tid = threadIdx.x;
    {
        const uint4* src = (const uint4*)Bf;
        uint4* dst = (uint4*)Bs;
        for (int i = tid; i < 8 * NT * 16; i += 256) dst[i] = src[i];
    }
    __syncthreads();

    const int warp = tid >> 5, lane = tid & 31;
    const int g = lane >> 2, tg = lane & 3;
    const int r0 = blockIdx.x * 128 + warp * 16 + g;
    const int r1 = r0 + 8;
    const bool v0 = r0 < M, v1 = r1 < M;

    float acc[NT][4];
#pragma unroll
    for (int t = 0; t < NT; t++)
#pragma unroll
        for (int c = 0; c < 4; c++) acc[t][c] = 0.f;

#pragma unroll 2
    for (int step = 0; step < 8; step++) {
        const int k0 = step * 16 + tg * 2;
        uint32_t a0 = 0, a1 = 0, a2 = 0, a3 = 0;
        if (AFP32) {
            const float* A0 = (const float*)Aptr + (size_t)r0 * 128;
            const float* A1 = (const float*)Aptr + (size_t)r1 * 128;
            if (v0) {
                float2 f0 = *(const float2*)(A0 + k0);
                float2 f1 = *(const float2*)(A0 + k0 + 8);
                __half2 h0 = __floats2half2_rn(f0.x, f0.y);
                __half2 h1 = __floats2half2_rn(f1.x, f1.y);
                a0 = *(uint32_t*)&h0; a2 = *(uint32_t*)&h1;
            }
            if (v1) {
                float2 f0 = *(const float2*)(A1 + k0);
                float2 f1 = *(const float2*)(A1 + k0 + 8);
                __half2 h0 = __floats2half2_rn(f0.x, f0.y);
                __half2 h1 = __floats2half2_rn(f1.x, f1.y);
                a1 = *(uint32_t*)&h0; a3 = *(uint32_t*)&h1;
            }
        } else {
            const __half* A0 = (const __half*)Aptr + (size_t)r0 * 128;
            const __half* A1 = (const __half*)Aptr + (size_t)r1 * 128;
            if (v0) { a0 = *(const uint32_t*)(A0 + k0); a2 = *(const uint32_t*)(A0 + k0 + 8); }
            if (v1) { a1 = *(const uint32_t*)(A1 + k0); a3 = *(const uint32_t*)(A1 + k0 + 8); }
        }
        const uint32_t* bp = Bs + step * (NT * 64) + lane * 2;
#pragma unroll
        for (int t = 0; t < NT; t++) {
            uint2 b = *(const uint2*)(bp + t * 64);
            mma16(acc[t], a0, a1, a2, a3, b.x, b.y);
        }
    }

#pragma unroll
    for (int t = 0; t < NT; t++) {
        const int j = t * 8 + tg * 2;
        if (j < nhw) {
            float2 w0 = make_float2(acc[t][0], acc[t][1]);
            float2 w1 = make_float2(acc[t][2], acc[t][3]);
            if (bias) {
                float bx = bias[j], by = bias[j + 1];
                w0.x += bx; w0.y += by; w1.x += bx; w1.y += by;
            }
            if (elu_out) {
                w0.x = eluf(w0.x); w0.y = eluf(w0.y);
                w1.x = eluf(w1.x); w1.y = eluf(w1.y);
            }
            if (OUTHALF) {
                __half* C = (__half*)Cptr;
                if (v0) *(__half2*)(C + (size_t)r0 * nhw + j) = __floats2half2_rn(w0.x, w0.y);
                if (v1) *(__half2*)(C + (size_t)r1 * nhw + j) = __floats2half2_rn(w1.x, w1.y);
            } else {
                float* C = (float*)Cptr;
                if (v0) *(float2*)(C + (size_t)r0 * nhw + j) = w0;
                if (v1) *(float2*)(C + (size_t)r1 * nhw + j) = w1;
            }
        } else if (write_s) {
            const int d = j - nhw;
            if (d < 4) {
                if (v0) { Ss[r0 * 4 + d] = acc[t][0]; Ss[r0 * 4 + d + 1] = acc[t][1]; }
                if (v1) { Ss[r1 * 4 + d] = acc[t][2]; Ss[r1 * 4 + d + 1] = acc[t][3]; }
            } else if (d < 8) {
                if (v0) { Sd[r0 * 4 + d - 4] = acc[t][0]; Sd[r0 * 4 + d - 3] = acc[t][1]; }
                if (v1) { Sd[r1 * 4 + d - 4] = acc[t][2]; Sd[r1 * 4 + d - 3] = acc[t][3]; }
            }
        }
    }
}

// ---------------- aggregation: warp per node, two-phase chunked ----------------
__global__ void __launch_bounds__(256)
agg_hidden_kernel(__half* __restrict__ out) {
    __shared__ float4 s_w[8][32];
    __shared__ int    s_c[8][32];
    const int warp = threadIdx.x >> 5, lane = threadIdx.x & 31;
    const int node = blockIdx.x * 8 + warp;
    if (node >= NN) return;
    const int s = g_rp[node], e = g_rp[node + 1];
    uint2* op = (uint2*)(out + (size_t)node * 128);
    if (s == e) { op[lane] = make_uint2(0u, 0u); return; }
    const float4 as = ((const float4*)g_ss)[node];
    const int head = lane >> 3;

    float l0 = -1e30f, l1 = -1e30f, l2 = -1e30f, l3 = -1e30f;
    int c0 = 0;
    const int my0 = s + lane;
    if (my0 < e) {
        c0 = g_col[my0];
        float4 sd = ((const float4*)g_sd)[c0];
        l0 = lreluf(as.x + sd.x); l1 = lreluf(as.y + sd.y);
        l2 = lreluf(as.z + sd.z); l3 = lreluf(as.w + sd.w);
    }
    float m0 = l0, m1 = l1, m2 = l2, m3 = l3;
    for (int ei = s + 32 + lane; ei < e; ei += 32) {
        int c = g_col[ei];
        float4 sd = ((const float4*)g_sd)[c];
        m0 = fmaxf(m0, lreluf(as.x + sd.x));
        m1 = fmaxf(m1, lreluf(as.y + sd.y));
        m2 = fmaxf(m2, lreluf(as.z + sd.z));
        m3 = fmaxf(m3, lreluf(as.w + sd.w));
    }
#pragma unroll
    for (int o = 16; o > 0; o >>= 1) {
        m0 = fmaxf(m0, __shfl_xor_sync(~0u, m0, o));
        m1 = fmaxf(m1, __shfl_xor_sync(~0u, m1, o));
        m2 = fmaxf(m2, __shfl_xor_sync(~0u, m2, o));
        m3 = fmaxf(m3, __shfl_xor_sync(~0u, m3, o));
    }

    float4 acc = make_float4(0.f, 0.f, 0.f, 0.f);
    float sw0 = 0.f, sw1 = 0.f, sw2 = 0.f, sw3 = 0.f;
    for (int cs = s; cs < e; cs += 32) {
        const int my = cs + lane;
        float w0 = 0.f, w1 = 0.f, w2 = 0.f, w3 = 0.f;
        int c = 0;
        if (my < e) {
            if (cs == s) {
                c = c0;
                w0 = __expf(l0 - m0); w1 = __expf(l1 - m1);
                w2 = __expf(l2 - m2); w3 = __expf(l3 - m3);
            } else {
                c = g_col[my];
                float4 sd = ((const float4*)g_sd)[c];
                w0 = __expf(lreluf(as.x + sd.x) - m0);
                w1 = __expf(lreluf(as.y + sd.y) - m1);
                w2 = __expf(lreluf(as.z + sd.z) - m2);
                w3 = __expf(lreluf(as.w + sd.w) - m3);
            }
            sw0 += w0; sw1 += w1; sw2 += w2; sw3 += w3;
        }
        s_w[warp][lane] = make_float4(w0, w1, w2, w3);
        s_c[warp][lane] = c;
        __syncwarp();
        const int n = min(32, e - cs);
        for (int j = 0; j < n; j++) {
            const int cc = s_c[warp][j];
            const float w = ((const float*)&s_w[warp][j])[head];
            const float4 hr = ((const float4*)(g_hw + (size_t)cc * 128))[lane];
            acc.x += w * hr.x; acc.y += w * hr.y;
            acc.z += w * hr.z; acc.w += w * hr.w;
        }
        __syncwarp();
    }
#pragma unroll
    for (int o = 16; o > 0; o >>= 1) {
        sw0 += __shfl_xor_sync(~0u, sw0, o);
        sw1 += __shfl_xor_sync(~0u, sw1, o);
        sw2 += __shfl_xor_sync(~0u, sw2, o);
        sw3 += __shfl_xor_sync(~0u, sw3, o);
    }
    const float swh = (head == 0) ? sw0 : (head == 1) ? sw1 : (head == 2) ? sw2 : sw3;
    const float inv = __fdividef(1.f, swh);
    __half2 h0 = __floats2half2_rn(eluf(acc.x * inv), eluf(acc.y * inv));
    __half2 h1 = __floats2half2_rn(eluf(acc.z * inv), eluf(acc.w * inv));
    op[lane] = make_uint2(*(uint32_t*)&h0, *(uint32_t*)&h1);
}

__global__ void __launch_bounds__(256)
agg_final_kernel(float* __restrict__ out) {
    __shared__ float s_w[8][32];
    __shared__ int   s_c[8][32];
    const int warp = threadIdx.x >> 5, lane = threadIdx.x & 31;
    const int node = blockIdx.x * 8 + warp;
    if (node >= NN) return;
    const int s = g_rp[node], e = g_rp[node + 1];
    float2* op = (float2*)(out + (size_t)node * 64);
    if (s == e) { op[lane] = make_float2(0.f, 0.f); return; }
    const float as = g_ss[node * 4];

    float l0 = -1e30f;
    int c0 = 0;
    const int my0 = s + lane;
    if (my0 < e) { c0 = g_col[my0]; l0 = lreluf(as + g_sd[c0 * 4]); }
    float mm = l0;
    for (int ei = s + 32 + lane; ei < e; ei += 32)
        mm = fmaxf(mm, lreluf(as + g_sd[g_col[ei] * 4]));
#pragma unroll
    for (int o = 16; o > 0; o >>= 1) mm = fmaxf(mm, __shfl_xor_sync(~0u, mm, o));

    float2 acc = make_float2(0.f, 0.f);
    float sw = 0.f;
    for (int cs = s; cs < e; cs += 32) {
        const int my = cs + lane;
        float w = 0.f;
        int c = 0;
        if (my < e) {
            if (cs == s) { c = c0; w = __expf(l0 - mm); }
            else { c = g_col[my]; w = __expf(lreluf(as + g_sd[c * 4]) - mm); }
            sw += w;
        }
        s_w[warp][lane] = w;
        s_c[warp][lane] = c;
        __syncwarp();
        const int n = min(32, e - cs);
        for (int j = 0; j < n; j++) {
            const int cc = s_c[warp][j];
            const float w2 = s_w[warp][j];
            const float2 hr = ((const float2*)(g_hw + (size_t)cc * 64))[lane];
            acc.x += w2 * hr.x; acc.y += w2 * hr.y;
        }
        __syncwarp();
    }
#pragma unroll
    for (int o = 16; o > 0; o >>= 1) sw += __shfl_xor_sync(~0u, sw, o);
    const float inv = __fdividef(1.f, sw);
    op[lane] = make_float2(acc.x * inv, acc.y * inv);
}

// ---------------- launch ----------------
extern "C" void kernel_launch(void* const* d_in, const int* in_sizes, int n_in,
                              void* d_out, int out_size) {
    const float* x     = (const float*)d_in[0];
    const int*   ei    = (const int*)d_in[1];
    const float* Win   = (const float*)d_in[2];
    const float* b_in  = (const float*)d_in[3];
    const float* a_hid = (const float*)d_in[4];
    const float* W_hid = (const float*)d_in[5];
    const float* a_out = (const float*)d_in[6];
    const float* W_out = (const float*)d_in[7];
    float* out = (float*)d_out;
    (void)in_sizes; (void)n_in; (void)out_size;

    static cudaStream_t s2 = nullptr;
    static cudaEvent_t evA = nullptr, evB = nullptr;
    static bool inited = false;
    if (!inited) {
        cudaStreamCreateWithFlags(&s2, cudaStreamNonBlocking);
        cudaEventCreateWithFlags(&evA, cudaEventDisableTiming);
        cudaEventCreateWithFlags(&evB, cudaEventDisableTiming);
        cudaFuncSetAttribute(gemm_tc<16, true, true>,
                             cudaFuncAttributeMaxDynamicSharedMemorySize, 8 * 16 * 64 * 4);
        cudaFuncSetAttribute(gemm_tc<17, false, false>,
                             cudaFuncAttributeMaxDynamicSharedMemorySize, 8 * 17 * 64 * 4);
        cudaFuncSetAttribute(gemm_tc<9, false, false>,
                             cudaFuncAttributeMaxDynamicSharedMemorySize, 8 * 9 * 64 * 4);
        inited = true;
    }

    __half* pre;
    float *hw, *ss, *sd;
    uint32_t* bbase;
    cudaGetSymbolAddress((void**)&pre, g_pre);
    cudaGetSymbolAddress((void**)&hw, g_hw);
    cudaGetSymbolAddress((void**)&ss, g_ss);
    cudaGetSymbolAddress((void**)&sd, g_sd);
    cudaGetSymbolAddress((void**)&bbase, g_B);
    uint32_t* B0 = bbase;
    uint32_t* B1 = bbase + BSTRIDE;
    uint32_t* B2 = bbase + 2 * BSTRIDE;
    uint32_t* B3 = bbase + 3 * BSTRIDE;

    const int gx = (NN + 127) / 128;
    const int ga = (NN + 7) / 8;

    // fork point (s2 depends only on harness-ready inputs)
    cudaEventRecord(evA, 0);
    cudaStreamWaitEvent(s2, evA, 0);

    // launch #1..#2 (main): pack + input GEMM
    pack_kernel<<<(4 * 8 * 17 * 64 + 255) / 256, 256>>>(Win, a_hid, W_hid, a_out, W_out);
    gemm_tc<16, true, true><<<gx, 256, 8 * 16 * 64 * 4>>>(x, B0, pre, nullptr, nullptr, b_in, NN, 128, 1, 0);

    // launch #3 (s2): degree count (g_deg zero by invariant)
    count_deg_kernel<<<(EE + 255) / 256, 256, 0, s2>>>(ei);

    // launch #4 (main): hidden-layer GEMM  <-- ncu capture slot
    gemm_tc<17, false, false><<<gx, 256, 8 * 17 * 64 * 4>>>(pre, B1, hw, ss, sd, nullptr, NN, 128, 0, 1);

    // launches #5..#7 (s2): rest of CSR build
    scan_partial_kernel<<<(NN + 1023) / 1024, 1024, 0, s2>>>();
    scan_apply_kernel<<<(NN + 1023) / 1024, 1024, 0, s2>>>();
    fill_csr_kernel<<<(EE + 255) / 256, 256, 0, s2>>>(ei);
    cudaEventRecord(evB, s2);

    // join: aggregation needs the CSR
    cudaStreamWaitEvent(0, evB, 0);
    agg_hidden_kernel<<<ga, 256>>>(pre);
    gemm_tc<17, false, false><<<gx, 256, 8 * 17 * 64 * 4>>>(pre, B2, hw, ss, sd, nullptr, NN, 128, 0, 1);
    agg_hidden_kernel<<<ga, 256>>>(pre);
    gemm_tc<9, false, false><<<gx, 256, 8 * 9 * 64 * 4>>>(pre, B3, hw, ss, sd, nullptr, NN, 64, 0, 1);
    agg_final_kernel<<<ga, 256>>>(out);
}